// round 2
// baseline (speedup 1.0000x reference)
#include <cuda_runtime.h>
#include <cuda_bf16.h>

#define NP 8          // preds per block (one warp each)
#define NT 128        // targets per block tile (32 float4 per warp)
#define EPS 1e-6f
#define MAXC 16

__device__ __forceinline__ float cost_one(
    float pcx, float pcy, float pw, float ph,
    float px0, float py0, float px1, float py1, float pa,
    const float* __restrict__ prob,
    float tcx, float tcy, float tw, float th,
    float tx0, float ty0, float tx1, float ty1, float ta,
    int tl)
{
    // L1 on cxcywh
    float l1 = fabsf(pcx - tcx) + fabsf(pcy - tcy) + fabsf(pw - tw) + fabsf(ph - th);
    // IoU
    float iw = fminf(px1, tx1) - fmaxf(px0, tx0);
    float ih = fminf(py1, ty1) - fmaxf(py0, ty0);
    iw = fmaxf(iw, 0.0f); ih = fmaxf(ih, 0.0f);
    float inter = iw * ih;
    float uni = pa + ta - inter;
    float iou = __fdividef(inter, uni + EPS);
    // enclosing box
    float cw = fmaxf(px1, tx1) - fminf(px0, tx0);
    float ch = fmaxf(py1, ty1) - fminf(py0, ty0);
    cw = fmaxf(cw, 0.0f); ch = fmaxf(ch, 0.0f);
    float ac = cw * ch;
    float giou = iou - __fdividef(ac - uni, ac + EPS);
    // C = 1*(-prob) + 5*l1 + 2*(-giou)
    return -prob[tl] + 5.0f * l1 - 2.0f * giou;
}

__global__ __launch_bounds__(256, 4)
void hungarian_cost_kernel(
    const float* __restrict__ logits,   // [N, C]
    const float* __restrict__ pboxes,   // [N, 4] cxcywh
    const int*   __restrict__ tlabels,  // [T]
    const float* __restrict__ tboxes,   // [T, 4] cxcywh
    float* __restrict__ out,            // [N, T]
    int C, int T)
{
    __shared__ __align__(16) float s_prob[NP][12];   // stride 12 -> labels 0..10 hit distinct banks
    __shared__ float s_pcx[NP], s_pcy[NP], s_pw[NP], s_ph[NP];
    __shared__ float s_px0[NP], s_py0[NP], s_px1[NP], s_py1[NP], s_pa[NP];
    __shared__ __align__(16) float s_tcx[NT], s_tcy[NT], s_tw[NT], s_th[NT];
    __shared__ __align__(16) float s_tx0[NT], s_ty0[NT], s_tx1[NT], s_ty1[NT], s_ta[NT];
    __shared__ __align__(16) int   s_tl[NT];

    const int tid    = threadIdx.x;
    const int t_base = blockIdx.x * NT;
    const int n_base = blockIdx.y * NP;

    // ---- load/precompute phase ----
    if (tid < NT) {
        int t = t_base + tid;
        float4 b = reinterpret_cast<const float4*>(tboxes)[t];
        s_tcx[tid] = b.x; s_tcy[tid] = b.y; s_tw[tid] = b.z; s_th[tid] = b.w;
        s_tx0[tid] = b.x - 0.5f * b.z;
        s_ty0[tid] = b.y - 0.5f * b.w;
        s_tx1[tid] = b.x + 0.5f * b.z;
        s_ty1[tid] = b.y + 0.5f * b.w;
        s_ta[tid]  = b.z * b.w;
        s_tl[tid]  = tlabels[t];
    } else if (tid < NT + NP) {
        int p = tid - NT;
        int n = n_base + p;
        const float* lg = logits + (size_t)n * C;
        float mx = -1e30f;
        #pragma unroll 4
        for (int c = 0; c < C; c++) mx = fmaxf(mx, lg[c]);
        float e[MAXC];
        float s = 0.0f;
        #pragma unroll 4
        for (int c = 0; c < C; c++) { e[c] = __expf(lg[c] - mx); s += e[c]; }
        float inv = __frcp_rn(s);
        #pragma unroll 4
        for (int c = 0; c < C; c++) s_prob[p][c] = e[c] * inv;

        float4 b = reinterpret_cast<const float4*>(pboxes)[n];
        s_pcx[p] = b.x; s_pcy[p] = b.y; s_pw[p] = b.z; s_ph[p] = b.w;
        s_px0[p] = b.x - 0.5f * b.z;
        s_py0[p] = b.y - 0.5f * b.w;
        s_px1[p] = b.x + 0.5f * b.z;
        s_py1[p] = b.y + 0.5f * b.w;
        s_pa[p]  = b.z * b.w;
    }
    __syncthreads();

    // ---- compute phase: warp p handles pred row p, lane handles 4 targets ----
    const int p    = tid >> 5;
    const int lane = tid & 31;

    const float pcx = s_pcx[p], pcy = s_pcy[p], pw = s_pw[p], ph = s_ph[p];
    const float px0 = s_px0[p], py0 = s_py0[p], px1 = s_px1[p], py1 = s_py1[p];
    const float pa  = s_pa[p];
    const float* prob = s_prob[p];

    const float4 tcx = reinterpret_cast<const float4*>(s_tcx)[lane];
    const float4 tcy = reinterpret_cast<const float4*>(s_tcy)[lane];
    const float4 tw  = reinterpret_cast<const float4*>(s_tw )[lane];
    const float4 th  = reinterpret_cast<const float4*>(s_th )[lane];
    const float4 tx0 = reinterpret_cast<const float4*>(s_tx0)[lane];
    const float4 ty0 = reinterpret_cast<const float4*>(s_ty0)[lane];
    const float4 tx1 = reinterpret_cast<const float4*>(s_tx1)[lane];
    const float4 ty1 = reinterpret_cast<const float4*>(s_ty1)[lane];
    const float4 ta  = reinterpret_cast<const float4*>(s_ta )[lane];
    const int4   tl  = reinterpret_cast<const int4*>(s_tl)[lane];

    float4 o;
    o.x = cost_one(pcx,pcy,pw,ph, px0,py0,px1,py1,pa, prob,
                   tcx.x,tcy.x,tw.x,th.x, tx0.x,ty0.x,tx1.x,ty1.x,ta.x, tl.x);
    o.y = cost_one(pcx,pcy,pw,ph, px0,py0,px1,py1,pa, prob,
                   tcx.y,tcy.y,tw.y,th.y, tx0.y,ty0.y,tx1.y,ty1.y,ta.y, tl.y);
    o.z = cost_one(pcx,pcy,pw,ph, px0,py0,px1,py1,pa, prob,
                   tcx.z,tcy.z,tw.z,th.z, tx0.z,ty0.z,tx1.z,ty1.z,ta.z, tl.z);
    o.w = cost_one(pcx,pcy,pw,ph, px0,py0,px1,py1,pa, prob,
                   tcx.w,tcy.w,tw.w,th.w, tx0.w,ty0.w,tx1.w,ty1.w,ta.w, tl.w);

    float* row = out + (size_t)(n_base + p) * T + t_base;
    reinterpret_cast<float4*>(row)[lane] = o;
}

extern "C" void kernel_launch(void* const* d_in, const int* in_sizes, int n_in,
                              void* d_out, int out_size)
{
    const float* logits  = (const float*)d_in[0];   // [B*Q, C] fp32
    const float* pboxes  = (const float*)d_in[1];   // [B*Q, 4] fp32
    const int*   tlabels = (const int*)  d_in[2];   // [T] int32
    const float* tboxes  = (const float*)d_in[3];   // [T, 4] fp32

    const int T = in_sizes[2];          // 3200
    const int N = in_sizes[1] / 4;      // 9600
    const int C = in_sizes[0] / N;      // 11

    dim3 grid(T / NT, N / NP);          // (25, 1200)
    hungarian_cost_kernel<<<grid, 256>>>(logits, pboxes, tlabels, tboxes,
                                         (float*)d_out, C, T);
}

// round 3
// speedup vs baseline: 1.9319x; 1.9319x over previous
#include <cuda_runtime.h>
#include <cuda_bf16.h>

#define PB 64      // preds per block
#define TB 128     // targets per block tile
#define EPS 1e-6f
#define MAXC 16

// Cost for one (pred, target) pair. Pred quantities are warp-uniform scalars,
// target quantities are per-lane registers.
__device__ __forceinline__ float cost_one(
    float pcx, float pcy, float pw, float ph,
    float px0, float py0, float px1, float py1, float pa,
    float probv,
    float tcx, float tcy, float tw, float th,
    float tx0, float ty0, float tx1, float ty1, float ta)
{
    // L1 on cxcywh (4 subs + 3 adds-with-|src|)
    float l1 = (fabsf(pcx - tcx) + fabsf(pcy - tcy)) +
               (fabsf(pw  - tw ) + fabsf(ph  - th ));
    // intersection
    float iw = fminf(px1, tx1) - fmaxf(px0, tx0);
    float ih = fminf(py1, ty1) - fmaxf(py0, ty0);
    iw = fmaxf(iw, 0.0f); ih = fmaxf(ih, 0.0f);
    float inter = iw * ih;
    float uni = (pa + ta) - inter;
    // enclosing box (wh provably >= 0 for valid cxcywh boxes -> no clamp)
    float cw = fmaxf(px1, tx1) - fminf(px0, tx0);
    float ch = fmaxf(py1, ty1) - fminf(py0, ty0);
    float ac = cw * ch;
    // giou = iou - (ac-uni)/(ac+eps) = inter/d1 - 1 + d1/d2, one rcp:
    float d1 = uni + EPS;
    float d2 = ac + EPS;
    float r  = __frcp_rn(d1 * d2);
    float iou  = inter * d2 * r;
    float frac = d1 * d1 * r;          // d1/d2
    float giou = (iou - 1.0f) + frac;
    // C = -prob + 5*l1 - 2*giou
    return fmaf(-2.0f, giou, fmaf(5.0f, l1, -probv));
}

__global__ __launch_bounds__(256)
void hungarian_cost_kernel(
    const float* __restrict__ logits,   // [N, C]
    const float* __restrict__ pboxes,   // [N, 4] cxcywh
    const int*   __restrict__ tlabels,  // [T]
    const float* __restrict__ tboxes,   // [T, 4] cxcywh
    float* __restrict__ out,            // [N, T]
    int C, int T)
{
    __shared__ float s_pred[PB][10];               // cx,cy,w,h,x0,y0,x1,y1,area
    __shared__ float s_prob[PB][12];               // softmax probs, pad 12

    const int tid    = threadIdx.x;
    const int lane   = tid & 31;
    const int wrp    = tid >> 5;                   // 0..7
    const int t_base = blockIdx.x * TB;
    const int n_base = blockIdx.y * PB;

    // ---- prolog: per-pred softmax + box precompute (threads 0..63) ----
    if (tid < PB) {
        const int n = n_base + tid;
        const float* lg = logits + (size_t)n * C;
        float mx = -1e30f;
        #pragma unroll 4
        for (int c = 0; c < C; c++) mx = fmaxf(mx, lg[c]);
        float e[MAXC];
        float s = 0.0f;
        #pragma unroll 4
        for (int c = 0; c < C; c++) { e[c] = __expf(lg[c] - mx); s += e[c]; }
        float inv = __frcp_rn(s);
        #pragma unroll 4
        for (int c = 0; c < C; c++) s_prob[tid][c] = e[c] * inv;

        float4 b = reinterpret_cast<const float4*>(pboxes)[n];
        s_pred[tid][0] = b.x;  s_pred[tid][1] = b.y;
        s_pred[tid][2] = b.z;  s_pred[tid][3] = b.w;
        s_pred[tid][4] = b.x - 0.5f * b.z;
        s_pred[tid][5] = b.y - 0.5f * b.w;
        s_pred[tid][6] = b.x + 0.5f * b.z;
        s_pred[tid][7] = b.y + 0.5f * b.w;
        s_pred[tid][8] = b.z * b.w;
    }

    // ---- load 4 targets/lane into registers (once per block) ----
    const int t0 = t_base + lane * 4;
    const float4* tb4 = reinterpret_cast<const float4*>(tboxes);
    float4 b0 = tb4[t0 + 0], b1 = tb4[t0 + 1], b2 = tb4[t0 + 2], b3 = tb4[t0 + 3];
    int4 tl4 = reinterpret_cast<const int4*>(tlabels)[t0 >> 2];

    float tcx[4] = {b0.x, b1.x, b2.x, b3.x};
    float tcy[4] = {b0.y, b1.y, b2.y, b3.y};
    float twd[4] = {b0.z, b1.z, b2.z, b3.z};
    float tht[4] = {b0.w, b1.w, b2.w, b3.w};
    float tx0[4], ty0[4], tx1[4], ty1[4], ta[4];
    int   tl[4]  = {tl4.x, tl4.y, tl4.z, tl4.w};
    #pragma unroll
    for (int j = 0; j < 4; j++) {
        tx0[j] = tcx[j] - 0.5f * twd[j];
        ty0[j] = tcy[j] - 0.5f * tht[j];
        tx1[j] = tcx[j] + 0.5f * twd[j];
        ty1[j] = tcy[j] + 0.5f * tht[j];
        ta[j]  = twd[j] * tht[j];
    }

    __syncthreads();

    // ---- main loop: each warp handles 8 contiguous preds ----
    const int p_first = wrp * (PB / 8);
    float* orow = out + (size_t)(n_base + p_first) * T + t_base;

    #pragma unroll 2
    for (int i = 0; i < PB / 8; i++) {
        const float* pr   = s_pred[p_first + i];
        const float* prob = s_prob[p_first + i];
        const float pcx = pr[0], pcy = pr[1], pw = pr[2], ph = pr[3];
        const float px0 = pr[4], py0 = pr[5], px1 = pr[6], py1 = pr[7];
        const float pa  = pr[8];

        float4 o;
        o.x = cost_one(pcx,pcy,pw,ph, px0,py0,px1,py1,pa, prob[tl[0]],
                       tcx[0],tcy[0],twd[0],tht[0], tx0[0],ty0[0],tx1[0],ty1[0],ta[0]);
        o.y = cost_one(pcx,pcy,pw,ph, px0,py0,px1,py1,pa, prob[tl[1]],
                       tcx[1],tcy[1],twd[1],tht[1], tx0[1],ty0[1],tx1[1],ty1[1],ta[1]);
        o.z = cost_one(pcx,pcy,pw,ph, px0,py0,px1,py1,pa, prob[tl[2]],
                       tcx[2],tcy[2],twd[2],tht[2], tx0[2],ty0[2],tx1[2],ty1[2],ta[2]);
        o.w = cost_one(pcx,pcy,pw,ph, px0,py0,px1,py1,pa, prob[tl[3]],
                       tcx[3],tcy[3],twd[3],tht[3], tx0[3],ty0[3],tx1[3],ty1[3],ta[3]);

        reinterpret_cast<float4*>(orow)[lane] = o;
        orow += T;
    }
}

extern "C" void kernel_launch(void* const* d_in, const int* in_sizes, int n_in,
                              void* d_out, int out_size)
{
    const float* logits  = (const float*)d_in[0];   // [B*Q, C] fp32
    const float* pboxes  = (const float*)d_in[1];   // [B*Q, 4] fp32
    const int*   tlabels = (const int*)  d_in[2];   // [T] int32
    const float* tboxes  = (const float*)d_in[3];   // [T, 4] fp32

    const int T = in_sizes[2];          // 3200
    const int N = in_sizes[1] / 4;      // 9600
    const int C = in_sizes[0] / N;      // 11

    dim3 grid(T / TB, N / PB);          // (25, 150)
    hungarian_cost_kernel<<<grid, 256>>>(logits, pboxes, tlabels, tboxes,
                                         (float*)d_out, C, T);
}

// round 4
// speedup vs baseline: 1.9771x; 1.0234x over previous
#include <cuda_runtime.h>
#include <cuda_bf16.h>

#define PB 64      // preds per block
#define TB 128     // targets per block tile (4 per lane, as 2 f32x2 pairs)
#define EPS 1e-6f
#define MAXC 16

// ---- packed f32x2 helpers (sm_103a) ----
__device__ __forceinline__ float2 f2add(float2 a, float2 b) {
    float2 r;
    asm("add.rn.f32x2 %0, %1, %2;"
        : "=l"(reinterpret_cast<unsigned long long&>(r))
        : "l"(reinterpret_cast<unsigned long long&>(a)),
          "l"(reinterpret_cast<unsigned long long&>(b)));
    return r;
}
__device__ __forceinline__ float2 f2mul(float2 a, float2 b) {
    float2 r;
    asm("mul.rn.f32x2 %0, %1, %2;"
        : "=l"(reinterpret_cast<unsigned long long&>(r))
        : "l"(reinterpret_cast<unsigned long long&>(a)),
          "l"(reinterpret_cast<unsigned long long&>(b)));
    return r;
}
__device__ __forceinline__ float2 f2fma(float2 a, float2 b, float2 c) {
    float2 r;
    asm("fma.rn.f32x2 %0, %1, %2, %3;"
        : "=l"(reinterpret_cast<unsigned long long&>(r))
        : "l"(reinterpret_cast<unsigned long long&>(a)),
          "l"(reinterpret_cast<unsigned long long&>(b)),
          "l"(reinterpret_cast<unsigned long long&>(c)));
    return r;
}
__device__ __forceinline__ float frcp_fast(float x) {
    float r;
    asm("rcp.approx.f32 %0, %1;" : "=f"(r) : "f"(x));
    return r;
}

__global__ __launch_bounds__(256, 3)
void hungarian_cost_kernel(
    const float* __restrict__ logits,   // [N, C]
    const float* __restrict__ pboxes,   // [N, 4] cxcywh
    const int*   __restrict__ tlabels,  // [T]
    const float* __restrict__ tboxes,   // [T, 4] cxcywh
    float* __restrict__ out,            // [N, T]
    int C, int T)
{
    // pred row layout (duplicated for packed broadcast loads):
    // [cx,cx, cy,cy, w,w, h,h, x0,x0, y0,y0, x1,x1, y1,y1, paE,paE, pad,pad]
    __shared__ __align__(16) float s_pred[PB][20];
    __shared__ float s_prob[PB][12];

    const int tid    = threadIdx.x;
    const int lane   = tid & 31;
    const int wrp    = tid >> 5;
    const int t_base = blockIdx.x * TB;
    const int n_base = blockIdx.y * PB;

    // ---- prolog: per-pred softmax + duplicated box precompute ----
    if (tid < PB) {
        const int n = n_base + tid;
        const float* lg = logits + (size_t)n * C;
        float mx = -1e30f;
        #pragma unroll 4
        for (int c = 0; c < C; c++) mx = fmaxf(mx, lg[c]);
        float e[MAXC];
        float s = 0.0f;
        #pragma unroll 4
        for (int c = 0; c < C; c++) { e[c] = __expf(lg[c] - mx); s += e[c]; }
        float inv = __frcp_rn(s);
        #pragma unroll 4
        for (int c = 0; c < C; c++) s_prob[tid][c] = e[c] * inv;

        float4 b = reinterpret_cast<const float4*>(pboxes)[n];
        float x0 = b.x - 0.5f * b.z, y0 = b.y - 0.5f * b.w;
        float x1 = b.x + 0.5f * b.z, y1 = b.y + 0.5f * b.w;
        float paE = b.z * b.w + EPS;
        float* row = s_pred[tid];
        row[0]=b.x; row[1]=b.x;  row[2]=b.y; row[3]=b.y;
        row[4]=b.z; row[5]=b.z;  row[6]=b.w; row[7]=b.w;
        row[8]=x0;  row[9]=x0;   row[10]=y0; row[11]=y0;
        row[12]=x1; row[13]=x1;  row[14]=y1; row[15]=y1;
        row[16]=paE; row[17]=paE;
    }

    // ---- per-lane: 4 targets as 2 packed pairs (registers, once/block) ----
    const int t0 = t_base + lane * 4;
    const float4* tb4 = reinterpret_cast<const float4*>(tboxes);
    float4 b0 = tb4[t0 + 0], b1 = tb4[t0 + 1], b2 = tb4[t0 + 2], b3 = tb4[t0 + 3];
    int4 tl4 = reinterpret_cast<const int4*>(tlabels)[t0 >> 2];

    float2 Tcx[2] = {{b0.x, b1.x}, {b2.x, b3.x}};
    float2 Tcy[2] = {{b0.y, b1.y}, {b2.y, b3.y}};
    float2 Tw [2] = {{b0.z, b1.z}, {b2.z, b3.z}};
    float2 Th [2] = {{b0.w, b1.w}, {b2.w, b3.w}};
    float2 Tx0[2], Ty0[2], Tx1[2], Ty1[2], Ta[2];
    #pragma unroll
    for (int k = 0; k < 2; k++) {
        Tx0[k] = make_float2(fmaf(-0.5f, Tw[k].x, Tcx[k].x), fmaf(-0.5f, Tw[k].y, Tcx[k].y));
        Ty0[k] = make_float2(fmaf(-0.5f, Th[k].x, Tcy[k].x), fmaf(-0.5f, Th[k].y, Tcy[k].y));
        Tx1[k] = make_float2(fmaf( 0.5f, Tw[k].x, Tcx[k].x), fmaf( 0.5f, Tw[k].y, Tcx[k].y));
        Ty1[k] = make_float2(fmaf( 0.5f, Th[k].x, Tcy[k].x), fmaf( 0.5f, Th[k].y, Tcy[k].y));
        Ta[k]  = make_float2(Tw[k].x * Th[k].x, Tw[k].y * Th[k].y);
    }
    const int tl[4] = {tl4.x, tl4.y, tl4.z, tl4.w};

    const float2 neg1 = make_float2(-1.0f, -1.0f);
    const float2 five = make_float2( 5.0f,  5.0f);
    const float2 m2   = make_float2(-2.0f, -2.0f);
    const float2 eps2 = make_float2( EPS,   EPS);

    __syncthreads();

    // ---- main loop: warp handles 8 contiguous preds ----
    const int p_first = wrp * (PB / 8);
    float* orow = out + (size_t)(n_base + p_first) * T + t_base;

    #pragma unroll 2
    for (int i = 0; i < PB / 8; i++) {
        const float* rowp = s_pred[p_first + i];
        const float* prob = s_prob[p_first + i];
        const float4* pr4 = reinterpret_cast<const float4*>(rowp);
        float4 a0 = pr4[0];                 // cx,cx,cy,cy
        float4 a1 = pr4[1];                 // w,w,h,h
        float4 a2 = pr4[2];                 // x0,x0,y0,y0
        float4 a3 = pr4[3];                 // x1,x1,y1,y1
        float2 paE2 = *reinterpret_cast<const float2*>(rowp + 16);
        float2 pcx2 = make_float2(a0.x, a0.y), pcy2 = make_float2(a0.z, a0.w);
        float2 pw2  = make_float2(a1.x, a1.y), ph2  = make_float2(a1.z, a1.w);
        const float px0 = a2.x, py0 = a2.z, px1 = a3.x, py1 = a3.z;

        float2 ores[2];
        #pragma unroll
        for (int k = 0; k < 2; k++) {
            // L1 (packed subs, scalar abs-adds)
            float2 dcx = f2fma(Tcx[k], neg1, pcx2);
            float2 dcy = f2fma(Tcy[k], neg1, pcy2);
            float2 dw  = f2fma(Tw [k], neg1, pw2);
            float2 dh  = f2fma(Th [k], neg1, ph2);
            float l1x = (fabsf(dcx.x) + fabsf(dcy.x)) + (fabsf(dw.x) + fabsf(dh.x));
            float l1y = (fabsf(dcx.y) + fabsf(dcy.y)) + (fabsf(dw.y) + fabsf(dh.y));

            // intersection raw (scalar min/max -> packed)
            float2 mn1 = make_float2(fminf(px1, Tx1[k].x), fminf(px1, Tx1[k].y));
            float2 mx0 = make_float2(fmaxf(px0, Tx0[k].x), fmaxf(px0, Tx0[k].y));
            float2 mn1y = make_float2(fminf(py1, Ty1[k].x), fminf(py1, Ty1[k].y));
            float2 mx0y = make_float2(fmaxf(py0, Ty0[k].x), fmaxf(py0, Ty0[k].y));
            float2 iwr = f2fma(mx0,  neg1, mn1);    // may be negative
            float2 ihr = f2fma(mx0y, neg1, mn1y);
            float2 iw = make_float2(fmaxf(iwr.x, 0.0f), fmaxf(iwr.y, 0.0f));
            float2 ih = make_float2(fmaxf(ihr.x, 0.0f), fmaxf(ihr.y, 0.0f));
            float2 inter = f2mul(iw, ih);

            // enclosing box via identity: cw = (pw+tw) - iwr
            float2 sw = f2add(pw2, Tw[k]);
            float2 sh = f2add(ph2, Th[k]);
            float2 cw = f2fma(iwr, neg1, sw);
            float2 ch = f2fma(ihr, neg1, sh);

            float2 satE = f2add(paE2, Ta[k]);       // pa + ta + eps
            float2 d1 = f2fma(inter, neg1, satE);   // union + eps
            float2 d2 = f2fma(cw, ch, eps2);        // area_c + eps
            float2 prod = f2mul(d1, d2);
            float2 r2 = make_float2(frcp_fast(prod.x), frcp_fast(prod.y));

            float2 iou  = f2mul(f2mul(inter, d2), r2);
            float2 frac = f2mul(f2mul(d1, d1), r2);

            // C = (2 - prob) + 5*l1 - 2*frac - 2*iou
            float cxv = 2.0f - prob[tl[2*k]];
            float cyv = 2.0f - prob[tl[2*k + 1]];
            float2 base = f2fma(make_float2(l1x, l1y), five, make_float2(cxv, cyv));
            float2 acc  = f2fma(frac, m2, base);
            ores[k]     = f2fma(iou,  m2, acc);
        }

        reinterpret_cast<float4*>(orow)[lane] =
            make_float4(ores[0].x, ores[0].y, ores[1].x, ores[1].y);
        orow += T;
    }
}

extern "C" void kernel_launch(void* const* d_in, const int* in_sizes, int n_in,
                              void* d_out, int out_size)
{
    const float* logits  = (const float*)d_in[0];   // [B*Q, C] fp32
    const float* pboxes  = (const float*)d_in[1];   // [B*Q, 4] fp32
    const int*   tlabels = (const int*)  d_in[2];   // [T] int32
    const float* tboxes  = (const float*)d_in[3];   // [T, 4] fp32

    const int T = in_sizes[2];          // 3200
    const int N = in_sizes[1] / 4;      // 9600
    const int C = in_sizes[0] / N;      // 11

    dim3 grid(T / TB, N / PB);          // (25, 150)
    hungarian_cost_kernel<<<grid, 256>>>(logits, pboxes, tlabels, tboxes,
                                         (float*)d_out, C, T);
}

// round 5
// speedup vs baseline: 2.2113x; 1.1185x over previous
#include <cuda_runtime.h>
#include <cuda_bf16.h>

#define PB 64      // preds per block
#define TB 128     // targets per block (4 per lane)
#define EPS 1e-6f
#define MAXC 16
#define PSTRIDE 65 // prob table row stride (words) -> conflict-free gathers

__device__ __forceinline__ float frcp_fast(float x) {
    float r;
    asm("rcp.approx.f32 %0, %1;" : "=f"(r) : "f"(x));
    return r;
}

__global__ __launch_bounds__(256, 4)
void hungarian_cost_kernel(
    const float* __restrict__ logits,   // [N, C]
    const float* __restrict__ pboxes,   // [N, 4] cxcywh
    const int*   __restrict__ tlabels,  // [T]
    const float* __restrict__ tboxes,   // [T, 4] cxcywh
    float* __restrict__ out,            // [N, T]
    int C, int T)
{
    // pred row: [cx,cy,w,h][x0,y0,x1,y1][paE,pad,pad,pad]
    __shared__ __align__(16) float s_pred[PB][12];
    // transposed prob table: s_probT[c][p] = 2 - softmax(logits[p])[c]
    __shared__ float s_probT[11][PSTRIDE];

    const int tid    = threadIdx.x;
    const int lane   = tid & 31;
    const int wrp    = tid >> 5;
    const int t_base = blockIdx.x * TB;
    const int n_base = blockIdx.y * PB;

    // ---- prolog: per-pred softmax + box precompute (threads 0..63) ----
    if (tid < PB) {
        const int n = n_base + tid;
        const float* lg = logits + (size_t)n * C;
        float mx = -1e30f;
        #pragma unroll 4
        for (int c = 0; c < C; c++) mx = fmaxf(mx, lg[c]);
        float e[MAXC];
        float s = 0.0f;
        #pragma unroll 4
        for (int c = 0; c < C; c++) { e[c] = __expf(lg[c] - mx); s += e[c]; }
        float inv = __frcp_rn(s);
        #pragma unroll 4
        for (int c = 0; c < C; c++) s_probT[c][tid] = 2.0f - e[c] * inv;

        float4 b = reinterpret_cast<const float4*>(pboxes)[n];
        float* row = s_pred[tid];
        row[0] = b.x;  row[1] = b.y;  row[2] = b.z;  row[3] = b.w;
        row[4] = b.x - 0.5f * b.z;
        row[5] = b.y - 0.5f * b.w;
        row[6] = b.x + 0.5f * b.z;
        row[7] = b.y + 0.5f * b.w;
        row[8] = b.z * b.w + EPS;
    }

    // ---- per-lane: 4 targets in registers (once per block) ----
    const int t0 = t_base + lane * 4;
    const float4* tb4 = reinterpret_cast<const float4*>(tboxes);
    float4 b0 = tb4[t0 + 0], b1 = tb4[t0 + 1], b2 = tb4[t0 + 2], b3 = tb4[t0 + 3];
    int4 tl4 = reinterpret_cast<const int4*>(tlabels)[t0 >> 2];

    float tcx[4] = {b0.x, b1.x, b2.x, b3.x};
    float tcy[4] = {b0.y, b1.y, b2.y, b3.y};
    float twd[4] = {b0.z, b1.z, b2.z, b3.z};
    float tht[4] = {b0.w, b1.w, b2.w, b3.w};
    float tx0[4], ty0[4], tx1[4], ty1[4], ta[4];
    #pragma unroll
    for (int j = 0; j < 4; j++) {
        tx0[j] = fmaf(-0.5f, twd[j], tcx[j]);
        ty0[j] = fmaf(-0.5f, tht[j], tcy[j]);
        tx1[j] = fmaf( 0.5f, twd[j], tcx[j]);
        ty1[j] = fmaf( 0.5f, tht[j], tcy[j]);
        ta[j]  = twd[j] * tht[j];
    }

    __syncthreads();

    // gather base pointers: one per target, hot loop indexes with immediates
    const int p_first = wrp * (PB / 8);
    const float* gbase[4];
    #pragma unroll
    for (int j = 0; j < 4; j++)
        gbase[j] = &s_probT[0][0] + ((tl4.x * 0) /*keep types*/ , 0);
    {
        const int tl[4] = {tl4.x, tl4.y, tl4.z, tl4.w};
        #pragma unroll
        for (int j = 0; j < 4; j++)
            gbase[j] = &s_probT[tl[j]][p_first];
    }

    float* orow = out + (size_t)(n_base + p_first) * T + t_base + lane * 4;

    // ---- main loop: warp handles 8 contiguous preds, fully unrolled ----
    #pragma unroll
    for (int i = 0; i < PB / 8; i++) {
        const float* rowp = s_pred[p_first + i];
        const float4 a0 = reinterpret_cast<const float4*>(rowp)[0]; // cx,cy,w,h
        const float4 a1 = reinterpret_cast<const float4*>(rowp)[1]; // x0,y0,x1,y1
        const float paE = rowp[8];
        const float pcx = a0.x, pcy = a0.y, pw = a0.z, ph = a0.w;
        const float px0 = a1.x, py0 = a1.y, px1 = a1.z, py1 = a1.w;

        float o[4];
        #pragma unroll
        for (int j = 0; j < 4; j++) {
            // L1 (abs folded into FADD source modifiers)
            float dcx = pcx - tcx[j], dcy = pcy - tcy[j];
            float dw  = pw  - twd[j], dh  = ph  - tht[j];
            float l1  = (fabsf(dcx) + fabsf(dcy)) + (fabsf(dw) + fabsf(dh));
            // intersection
            float iw = fminf(px1, tx1[j]) - fmaxf(px0, tx0[j]);
            float ih = fminf(py1, ty1[j]) - fmaxf(py0, ty0[j]);
            iw = fmaxf(iw, 0.0f); ih = fmaxf(ih, 0.0f);
            float inter = iw * ih;
            // enclosing box (no clamp needed: cw >= pw >= 0)
            float cw = fmaxf(px1, tx1[j]) - fminf(px0, tx0[j]);
            float ch = fmaxf(py1, ty1[j]) - fminf(py0, ty0[j]);
            // one rcp for both ratios
            float d1 = (paE + ta[j]) - inter;       // union + eps
            float d2 = fmaf(cw, ch, EPS);           // area_c + eps
            float r  = frcp_fast(d1 * d2);
            float iou  = (inter * d2) * r;
            float frac = (d1 * d1) * r;             // d1/d2
            // C = (2 - prob) + 5*l1 - 2*iou - 2*frac
            float cxv = gbase[j][i];                // LDS [R + imm]
            float s0 = fmaf(5.0f, l1, cxv);
            float s1 = fmaf(-2.0f, iou, s0);
            o[j] = fmaf(-2.0f, frac, s1);
        }
        reinterpret_cast<float4*>(orow + (size_t)i * T)[0] =
            make_float4(o[0], o[1], o[2], o[3]);
    }
}

extern "C" void kernel_launch(void* const* d_in, const int* in_sizes, int n_in,
                              void* d_out, int out_size)
{
    const float* logits  = (const float*)d_in[0];   // [B*Q, C] fp32
    const float* pboxes  = (const float*)d_in[1];   // [B*Q, 4] fp32
    const int*   tlabels = (const int*)  d_in[2];   // [T] int32
    const float* tboxes  = (const float*)d_in[3];   // [T, 4] fp32

    const int T = in_sizes[2];          // 3200
    const int N = in_sizes[1] / 4;      // 9600
    const int C = in_sizes[0] / N;      // 11

    dim3 grid(T / TB, N / PB);          // (25, 150)
    hungarian_cost_kernel<<<grid, 256>>>(logits, pboxes, tlabels, tboxes,
                                         (float*)d_out, C, T);
}